// round 3
// baseline (speedup 1.0000x reference)
#include <cuda_runtime.h>
#include <cuda_bf16.h>
#include <math.h>

// Problem constants
#define BB 16
#define DD 1024
#define TT 1024
#define HH 1024
#define NC 3072   // 3*H channels (z|f|o)

// GEMM tiling
#define BM 128
#define BN 128
#define BK 16
#define TM 8
#define TN 8

// Scratch: activated gates [B*T, 3H]  (z=tanh, f=sigmoid, o=sigmoid) -- 192 MB
__device__ float g_gates[(size_t)BB * TT * NC];

// ---------------------------------------------------------------------------
// Kernel 1: gates = causal-conv-as-GEMM + bias + activation
//   C[m, n], m = b*T + t, n = channel c
//   C = x[b,:,t-1] @ W[:, :, 0]^T + x[b,:,t] @ W[:, :, 1]^T + bias
// Tile: 128x128, K-step 16 over d. 256 threads, 8x8 per thread.
// ---------------------------------------------------------------------------
__global__ __launch_bounds__(256, 2)
void qrnn_gemm_kernel(const float* __restrict__ x,     // [B, D, T]
                      const float* __restrict__ w,     // [3H, D, 2]
                      const float* __restrict__ bias)  // [3H]
{
    // As[kk][i] = x[b, d0+kk, t0-1+i], i in [0,129); padded to 132
    __shared__ __align__(16) float As[BK][BM + 4];
    // Bs[kk][k][nn] = w[n0+nn, d0+kk, k]; nn padded to 132 (16B-aligned rows)
    __shared__ __align__(16) float Bs[BK][2][BN + 4];

    const int mtile = blockIdx.x;           // 0..127 : (b, t0)
    const int ntile = blockIdx.y;           // 0..23
    const int b  = mtile >> 3;              // T/BM = 8 tiles per batch
    const int t0 = (mtile & 7) * BM;
    const int n0 = ntile * BN;

    const int tid = threadIdx.x;
    const int tx = tid & 15;                // n direction (8 cols each)
    const int ty = tid >> 4;                // m direction (8 rows each)

    const float* xb = x + (size_t)b * DD * TT;

    float acc[TM][TN];
#pragma unroll
    for (int i = 0; i < TM; ++i)
#pragma unroll
        for (int j = 0; j < TN; ++j) acc[i][j] = 0.f;

    for (int d0 = 0; d0 < DD; d0 += BK) {
        // ---- load A tile: 16 rows of 129 valid floats (t0-1 .. t0+127) ----
#pragma unroll
        for (int idx = tid; idx < BK * (BM + 4); idx += 256) {
            const int kk = idx / (BM + 4);
            const int i  = idx % (BM + 4);
            const int t  = t0 - 1 + i;
            float v = 0.f;
            if (i < BM + 1 && t >= 0) v = xb[(size_t)(d0 + kk) * TT + t];
            As[kk][i] = v;
        }
        // ---- load B tile: 128 channels x 16 d x 2 taps, via float2 ----
        {
            const int dd = tid & 15;
            const int c0 = tid >> 4;     // 0..15
#pragma unroll
            for (int it = 0; it < 8; ++it) {
                const int nn = c0 + it * 16;
                const float2 wv = *(const float2*)&w[(size_t)(n0 + nn) * (DD * 2) + (size_t)(d0 + dd) * 2];
                Bs[dd][0][nn] = wv.x;
                Bs[dd][1][nn] = wv.y;
            }
        }
        __syncthreads();

#pragma unroll
        for (int kk = 0; kk < BK; ++kk) {
            float a[TM + 1];
#pragma unroll
            for (int j = 0; j <= TM; ++j) a[j] = As[kk][ty * TM + j];

            float b0[TN], b1[TN];
#pragma unroll
            for (int j4 = 0; j4 < TN; j4 += 4) {
                const float4 v0 = *(const float4*)&Bs[kk][0][tx * TN + j4];
                b0[j4] = v0.x; b0[j4 + 1] = v0.y; b0[j4 + 2] = v0.z; b0[j4 + 3] = v0.w;
                const float4 v1 = *(const float4*)&Bs[kk][1][tx * TN + j4];
                b1[j4] = v1.x; b1[j4 + 1] = v1.y; b1[j4 + 2] = v1.z; b1[j4 + 3] = v1.w;
            }
#pragma unroll
            for (int i = 0; i < TM; ++i) {
#pragma unroll
                for (int j = 0; j < TN; ++j) {
                    // prev tap (t-1) * w0 + cur tap (t) * w1
                    acc[i][j] += a[i] * b0[j];
                    acc[i][j] += a[i + 1] * b1[j];
                }
            }
        }
        __syncthreads();
    }

    // ---- epilogue: bias + activation, store activated gates ----
    // Tile lies entirely in one region (boundaries at 1024/2048 are multiples of 128)
    const bool is_z = (n0 < HH);   // tanh for z region, sigmoid for f and o
    float breg[TN];
#pragma unroll
    for (int j = 0; j < TN; ++j) breg[j] = bias[n0 + tx * TN + j];

#pragma unroll
    for (int i = 0; i < TM; ++i) {
        const size_t m = (size_t)mtile * BM + ty * TM + i;   // = b*T + t
        float vrow[TN];
#pragma unroll
        for (int j = 0; j < TN; ++j) {
            const float g = acc[i][j] + breg[j];
            vrow[j] = is_z ? tanhf(g) : (1.f / (1.f + expf(-g)));
        }
#pragma unroll
        for (int j4 = 0; j4 < TN; j4 += 4) {
            float4 v = make_float4(vrow[j4], vrow[j4 + 1], vrow[j4 + 2], vrow[j4 + 3]);
            *(float4*)&g_gates[m * NC + n0 + tx * TN + j4] = v;
        }
    }
}

// ---------------------------------------------------------------------------
// Kernel 2: fo-pooling scan. One thread per (b, h) chain.
//   c_t = f*c_{t-1} + (1-f)*z = f*(c_{t-1} - z) + z ;  h_t = o*c_t
// out layout: [c_seq (B,T,H)][h_seq (B,T,H)]
// ---------------------------------------------------------------------------
__global__ __launch_bounds__(256)
void qrnn_scan_kernel(float* __restrict__ out)
{
    const int gid = blockIdx.x * blockDim.x + threadIdx.x;   // 0..16383
    const int b = gid >> 10;
    const int h = gid & 1023;

    const float* __restrict__ g = g_gates + (size_t)b * TT * NC + h;
    float* __restrict__ cout = out + (size_t)b * TT * HH + h;
    float* __restrict__ hout = out + (size_t)BB * TT * HH + (size_t)b * TT * HH + h;

    float c = 0.f;
#pragma unroll 4
    for (int t = 0; t < TT; ++t) {
        const float* row = g + (size_t)t * NC;
        const float z = row[0];
        const float f = row[HH];
        const float o = row[2 * HH];
        c = f * (c - z) + z;
        cout[(size_t)t * HH] = c;
        hout[(size_t)t * HH] = o * c;
    }
}

// ---------------------------------------------------------------------------
extern "C" void kernel_launch(void* const* d_in, const int* in_sizes, int n_in,
                              void* d_out, int out_size)
{
    const float* x    = (const float*)d_in[0];   // [B, D, T]
    const float* w    = (const float*)d_in[1];   // [3H, D, 2]
    const float* bias = (const float*)d_in[2];   // [3H]
    float* out = (float*)d_out;

    dim3 grid((BB * TT) / BM, NC / BN);          // (128, 24)
    qrnn_gemm_kernel<<<grid, 256>>>(x, w, bias);

    qrnn_scan_kernel<<<(BB * HH) / 256, 256>>>(out);
}

// round 8
// speedup vs baseline: 3.7731x; 3.7731x over previous
#include <cuda_runtime.h>
#include <cuda_bf16.h>
#include <cstdint>
#include <math.h>

// ---------------------------------------------------------------------------
// Problem constants
// ---------------------------------------------------------------------------
#define BBATCH 16
#define DDIM   1024
#define TSEQ   1024
#define HDIM   1024
#define NCH    3072            // 3*H
#define MTOT   16384           // B*T
#define KCAT   6144            // 3 * (2*D) : [Ahi|Ahi|Alo] x [Bhi|Blo|Bhi]

// GEMM tiling
#define TILE_M 256
#define TILE_N 128
#define BKK    64
#define NKITER (KCAT / BKK)    // 96
#define NSTAGE 3

#define STAGE_BYTES  49152             // A 32KB + B 16KB
#define SM_A_OFF(s)  ((s) * STAGE_BYTES)
#define SM_B_OFF(s)  ((s) * STAGE_BYTES + 32768)
#define GEMM_SMEM    (NSTAGE * STAGE_BYTES)   // 147456

// ---------------------------------------------------------------------------
// Device scratch
// ---------------------------------------------------------------------------
__device__ __nv_bfloat16 g_A[(size_t)MTOT * KCAT];        // 192 MB
__device__ __nv_bfloat16 g_B[(size_t)NCH  * KCAT];        //  36 MB
__device__ float         g_gates[(size_t)MTOT * NCH];     // 192 MB (activated z|f|o)
__device__ float         g_state[(size_t)MTOT * 16 * 2];  // per-chunk (F, r)
__device__ float         g_cin[(size_t)MTOT * 16];        // per-chunk c_in

// ---------------------------------------------------------------------------
// PTX helpers (all plain sm_80-level: valid on sm_103 without 'a' features)
// ---------------------------------------------------------------------------
__device__ __forceinline__ void cp_async16(uint32_t dst, const void* src) {
    asm volatile("cp.async.cg.shared.global [%0], [%1], 16;" :: "r"(dst), "l"(src));
}
__device__ __forceinline__ void cp_commit() {
    asm volatile("cp.async.commit_group;" ::: "memory");
}

__device__ __forceinline__ void ldsm_x4(uint32_t* r, uint32_t addr) {
    asm volatile("ldmatrix.sync.aligned.m8n8.x4.shared.b16 {%0,%1,%2,%3}, [%4];"
                 : "=r"(r[0]), "=r"(r[1]), "=r"(r[2]), "=r"(r[3]) : "r"(addr));
}

__device__ __forceinline__ void mma16816(float* d, const uint32_t* a,
                                         uint32_t b0, uint32_t b1) {
    asm volatile(
        "mma.sync.aligned.m16n8k16.row.col.f32.bf16.bf16.f32 "
        "{%0,%1,%2,%3}, {%4,%5,%6,%7}, {%8,%9}, {%0,%1,%2,%3};"
        : "+f"(d[0]), "+f"(d[1]), "+f"(d[2]), "+f"(d[3])
        : "r"(a[0]), "r"(a[1]), "r"(a[2]), "r"(a[3]), "r"(b0), "r"(b1));
}

// ---------------------------------------------------------------------------
// prep_A: transpose x [B,D,T] -> A_cat bf16 [m=(b,t)][k], k = seg*2048+tap*1024+d
//   tap0 = x[t-1] (0 at t=0), tap1 = x[t];  segs: hi, hi, lo
// ---------------------------------------------------------------------------
__global__ __launch_bounds__(256)
void prep_A_kernel(const float* __restrict__ x) {
    __shared__ float tile[32][33];
    const int b  = blockIdx.z;
    const int t0 = blockIdx.x * 32;
    const int d0 = blockIdx.y * 32;
    const int tx = threadIdx.x;      // 0..31
    const int ty = threadIdx.y;      // 0..7

#pragma unroll
    for (int i = 0; i < 4; ++i) {
        const int dl = ty + i * 8;
        tile[dl][tx] = x[((size_t)b * DDIM + d0 + dl) * TSEQ + t0 + tx];
    }
    __syncthreads();

#pragma unroll
    for (int i = 0; i < 4; ++i) {
        const int tl = ty + i * 8;
        const float v = tile[tx][tl];
        const __nv_bfloat16 hi = __float2bfloat16(v);
        const __nv_bfloat16 lo = __float2bfloat16(v - __bfloat162float(hi));
        const int t = t0 + tl;
        const int d = d0 + tx;
        const size_t m1 = (size_t)b * TSEQ + t;      // row using x[t] as tap1
        g_A[m1 * KCAT + 1024 + d]        = hi;
        g_A[m1 * KCAT + 2048 + 1024 + d] = hi;
        g_A[m1 * KCAT + 4096 + 1024 + d] = lo;
        if (t + 1 < TSEQ) {                          // x[t] is tap0 of row t+1
            const size_t m0r = m1 + 1;
            g_A[m0r * KCAT + d]        = hi;
            g_A[m0r * KCAT + 2048 + d] = hi;
            g_A[m0r * KCAT + 4096 + d] = lo;
        }
        if (t == 0) {                                // causal pad: tap0 @ t=0
            const __nv_bfloat16 z = __float2bfloat16(0.f);
            g_A[m1 * KCAT + d]        = z;
            g_A[m1 * KCAT + 2048 + d] = z;
            g_A[m1 * KCAT + 4096 + d] = z;
        }
    }
}

// ---------------------------------------------------------------------------
// prep_B: w [3H, D, 2] -> B_cat bf16 [n][k], segs: hi, lo, hi
// ---------------------------------------------------------------------------
__global__ __launch_bounds__(512)
void prep_B_kernel(const float* __restrict__ w) {
    const int idx = blockIdx.x * 512 + threadIdx.x;   // over 3072*1024
    const int n = idx >> 10;
    const int d = idx & 1023;
    const float2 wv = *(const float2*)&w[(size_t)idx * 2];   // w[n][d][0..1]
#pragma unroll
    for (int tap = 0; tap < 2; ++tap) {
        const float v = tap ? wv.y : wv.x;
        const __nv_bfloat16 hi = __float2bfloat16(v);
        const __nv_bfloat16 lo = __float2bfloat16(v - __bfloat162float(hi));
        const size_t base = (size_t)n * KCAT + tap * 1024 + d;
        g_B[base]        = hi;
        g_B[base + 2048] = lo;
        g_B[base + 4096] = hi;
    }
}

// ---------------------------------------------------------------------------
// GEMM: g_gates = act( A_cat @ B_cat^T + bias )
// CTA 256x128, BK=64, 3-stage cp.async, warp-level bf16 mma.sync.
// smem tiles: K-major rows of 128B with SW128 xor swizzle (ldmatrix-friendly).
// ---------------------------------------------------------------------------
__device__ __forceinline__ void fill_stage(int kt, int s, int tid,
                                           uint32_t smem_base, int m0, int n0) {
    const char* Abase = (const char*)g_A;
    const char* Bbase = (const char*)g_B;
#pragma unroll
    for (int i = 0; i < 8; ++i) {                    // A: 2048 x 16B
        const int c   = tid + i * 256;
        const int row = c >> 3;
        const int cb  = (c & 7) << 4;
        const uint32_t off = (row << 7) + cb;
        const uint32_t sw  = off ^ ((off >> 3) & 0x70);
        cp_async16(smem_base + SM_A_OFF(s) + sw,
                   Abase + ((size_t)(m0 + row) * KCAT + kt * 64) * 2 + cb);
    }
#pragma unroll
    for (int i = 0; i < 4; ++i) {                    // B: 1024 x 16B
        const int c   = tid + i * 256;
        const int row = c >> 3;
        const int cb  = (c & 7) << 4;
        const uint32_t off = (row << 7) + cb;
        const uint32_t sw  = off ^ ((off >> 3) & 0x70);
        cp_async16(smem_base + SM_B_OFF(s) + sw,
                   Bbase + ((size_t)(n0 + row) * KCAT + kt * 64) * 2 + cb);
    }
    cp_commit();
}

__global__ __launch_bounds__(256, 1)
void qrnn_gemm_tc(const float* __restrict__ bias) {
    extern __shared__ __align__(1024) char smem[];
    const uint32_t smem_base = (uint32_t)__cvta_generic_to_shared(smem);
    const int tid = threadIdx.x;
    const int wid = tid >> 5;
    const int l   = tid & 31;
    const int n0 = blockIdx.x * TILE_N;   // n fastest: wave shares A m-panels + all of B in L2
    const int m0 = blockIdx.y * TILE_M;

    const int warp_m = wid & 3;           // 4 warps over M (64 rows each)
    const int warp_n = wid >> 2;          // 2 warps over N (64 cols each)

    // ldmatrix lane geometry (identical for A and B operand fetch):
    //   r=l&7 selects row-within-8, (l>>3)&1 selects +8 row, (l>>4)&1 selects +16B col
    const int r      = l & 7;
    const int rsel   = (l >> 3) & 1;
    const int csel   = (l >> 4) & 1;
    const uint32_t xorv = (uint32_t)r << 4;          // SW128 xor term (row&7 == r always)
    uint32_t kcx[4];
#pragma unroll
    for (int ks = 0; ks < 4; ++ks)
        kcx[ks] = ((uint32_t)(ks * 32 + 16 * csel)) ^ xorv;

    const uint32_t aRow = (uint32_t)(warp_m * 64 + r + 8 * rsel) << 7;
    const uint32_t bRow = (uint32_t)(warp_n * 64 + r + 8 * rsel) << 7;

    float acc[4][8][4];
#pragma unroll
    for (int mt = 0; mt < 4; ++mt)
#pragma unroll
        for (int nt = 0; nt < 8; ++nt)
#pragma unroll
            for (int q = 0; q < 4; ++q) acc[mt][nt][q] = 0.f;

    fill_stage(0, 0, tid, smem_base, m0, n0);
    fill_stage(1, 1, tid, smem_base, m0, n0);

    for (int kt = 0; kt < NKITER; ++kt) {
        const int s = kt % NSTAGE;
        if (kt + 2 < NKITER) {
            asm volatile("cp.async.wait_group 1;" ::: "memory");
        } else {
            asm volatile("cp.async.wait_group 0;" ::: "memory");
        }
        __syncthreads();

        const uint32_t aBase = smem_base + SM_A_OFF(s) + aRow;
        const uint32_t bBase = smem_base + SM_B_OFF(s) + bRow;

#pragma unroll
        for (int ks = 0; ks < 4; ++ks) {
            uint32_t a[4][4], bf[4][4];
#pragma unroll
            for (int mt = 0; mt < 4; ++mt)
                ldsm_x4(a[mt], aBase + mt * 2048 + kcx[ks]);
#pragma unroll
            for (int ng = 0; ng < 4; ++ng)
                ldsm_x4(bf[ng], bBase + ng * 2048 + kcx[ks]);
#pragma unroll
            for (int mt = 0; mt < 4; ++mt) {
#pragma unroll
                for (int ng = 0; ng < 4; ++ng) {
                    mma16816(acc[mt][2 * ng],     a[mt], bf[ng][0], bf[ng][2]);
                    mma16816(acc[mt][2 * ng + 1], a[mt], bf[ng][1], bf[ng][3]);
                }
            }
        }

        if (kt + 2 < NKITER)
            fill_stage(kt + 2, (kt + 2) % NSTAGE, tid, smem_base, m0, n0);
    }

    // ---- epilogue: bias + activation -> g_gates ----
    const int region = n0 >> 10;                 // 0=z(tanh), 1/2=sigmoid
    const int mW = m0 + warp_m * 64;
    const int nW = n0 + warp_n * 64;
#pragma unroll
    for (int mt = 0; mt < 4; ++mt) {
#pragma unroll
        for (int nt = 0; nt < 8; ++nt) {
            const int col  = nW + nt * 8 + 2 * (l & 3);
            const float b0 = bias[col];
            const float b1 = bias[col + 1];
#pragma unroll
            for (int half = 0; half < 2; ++half) {
                const int row = mW + mt * 16 + (l >> 2) + 8 * half;
                float gx = acc[mt][nt][2 * half]     + b0;
                float gy = acc[mt][nt][2 * half + 1] + b1;
                float vx, vy;
                if (region == 0) {
                    vx = 2.f / (1.f + __expf(-2.f * gx)) - 1.f;
                    vy = 2.f / (1.f + __expf(-2.f * gy)) - 1.f;
                } else {
                    vx = 1.f / (1.f + __expf(-gx));
                    vy = 1.f / (1.f + __expf(-gy));
                }
                *(float2*)&g_gates[(size_t)row * NCH + col] = make_float2(vx, vy);
            }
        }
    }
}

// ---------------------------------------------------------------------------
// Chunked fo-pooling scan: c_t = f*(c_{t-1} - z) + z ;  h_t = o*c_t
// 16 chunks of 64 per (b,h) chain -> 262K threads.
// ---------------------------------------------------------------------------
__global__ __launch_bounds__(256)
void qrnn_scan_pass1() {
    const int idx   = blockIdx.x * 256 + threadIdx.x;   // 0..262143
    const int b     = idx >> 14;
    const int chunk = (idx >> 10) & 15;
    const int h     = idx & 1023;
    const float* __restrict__ g =
        g_gates + ((size_t)(b * TSEQ + chunk * 64)) * NCH + h;
    float c = 0.f, F = 1.f;
#pragma unroll 4
    for (int t = 0; t < 64; ++t) {
        const float z = g[(size_t)t * NCH];
        const float f = g[(size_t)t * NCH + HDIM];
        c = f * (c - z) + z;
        F *= f;
    }
    const size_t st = ((size_t)(b * 1024 + h) * 16 + chunk) * 2;
    g_state[st]     = F;
    g_state[st + 1] = c;
}

__global__ __launch_bounds__(256)
void qrnn_scan_combine() {
    const int chain = blockIdx.x * 256 + threadIdx.x;   // 0..16383
    const float* st = g_state + (size_t)chain * 32;
    float* ci = g_cin + (size_t)chain * 16;
    float c = 0.f;
#pragma unroll
    for (int ch = 0; ch < 16; ++ch) {
        ci[ch] = c;
        c = st[ch * 2] * c + st[ch * 2 + 1];
    }
}

__global__ __launch_bounds__(256)
void qrnn_scan_pass2(float* __restrict__ out) {
    const int idx   = blockIdx.x * 256 + threadIdx.x;
    const int b     = idx >> 14;
    const int chunk = (idx >> 10) & 15;
    const int h     = idx & 1023;
    const float* __restrict__ g =
        g_gates + ((size_t)(b * TSEQ + chunk * 64)) * NCH + h;
    float* __restrict__ cout = out + ((size_t)b * TSEQ + chunk * 64) * HDIM + h;
    float* __restrict__ hout = cout + (size_t)BBATCH * TSEQ * HDIM;

    float c = g_cin[(size_t)(b * 1024 + h) * 16 + chunk];
#pragma unroll 4
    for (int t = 0; t < 64; ++t) {
        const float z = g[(size_t)t * NCH];
        const float f = g[(size_t)t * NCH + HDIM];
        const float o = g[(size_t)t * NCH + 2 * HDIM];
        c = f * (c - z) + z;
        cout[(size_t)t * HDIM] = c;
        hout[(size_t)t * HDIM] = o * c;
    }
}

// ---------------------------------------------------------------------------
extern "C" void kernel_launch(void* const* d_in, const int* in_sizes, int n_in,
                              void* d_out, int out_size)
{
    const float* x    = (const float*)d_in[0];   // [B, D, T]
    const float* w    = (const float*)d_in[1];   // [3H, D, 2]
    const float* bias = (const float*)d_in[2];   // [3H]
    float* out = (float*)d_out;

    cudaFuncSetAttribute(qrnn_gemm_tc, cudaFuncAttributeMaxDynamicSharedMemorySize,
                         GEMM_SMEM);

    prep_A_kernel<<<dim3(TSEQ / 32, DDIM / 32, BBATCH), dim3(32, 8)>>>(x);
    prep_B_kernel<<<(NCH * DDIM) / 512, 512>>>(w);

    qrnn_gemm_tc<<<dim3(NCH / TILE_N, MTOT / TILE_M), 256, GEMM_SMEM>>>(bias);

    qrnn_scan_pass1<<<(MTOT * 16) / 256, 256>>>();
    qrnn_scan_combine<<<MTOT / 256, 256>>>();
    qrnn_scan_pass2<<<(MTOT * 16) / 256, 256>>>(out);
}

// round 9
// speedup vs baseline: 3.9265x; 1.0407x over previous
#include <cuda_runtime.h>
#include <cuda_bf16.h>
#include <cstdint>
#include <math.h>

// ---------------------------------------------------------------------------
// Problem constants
// ---------------------------------------------------------------------------
#define BBATCH 16
#define DDIM   1024
#define TSEQ   1024
#define HDIM   1024
#define NCH    3072            // 3*H
#define MTOT   16384           // B*T
#define KCAT   6144            // logical K: 3 segs [Ahi|Ahi|Alo] x [Bhi|Blo|Bhi]
#define KA     4096            // physical A: [Ahi|Alo]
#define KB     4096            // physical B: [Bhi|Blo]

// GEMM tiling
#define TILE_M 256
#define TILE_N 128
#define BKK    64
#define NKITER (KCAT / BKK)    // 96 logical k-tiles
#define NSTAGE 4

#define STAGE_BYTES  49152             // A 32KB + B 16KB
#define SM_A_OFF(s)  ((s) * STAGE_BYTES)
#define SM_B_OFF(s)  ((s) * STAGE_BYTES + 32768)
#define GEMM_SMEM    (NSTAGE * STAGE_BYTES)   // 196608

// ---------------------------------------------------------------------------
// Device scratch
// ---------------------------------------------------------------------------
__device__ __nv_bfloat16 g_A[(size_t)MTOT * KA];          // 128 MB
__device__ __nv_bfloat16 g_B[(size_t)NCH  * KB];          //  24 MB
__device__ float         g_gates[(size_t)MTOT * NCH];     // 192 MB (activated z|f|o)
__device__ float         g_state[(size_t)MTOT * 16 * 2];  // per-chunk (F, r)
__device__ float         g_cin[(size_t)MTOT * 16];        // per-chunk c_in

// ---------------------------------------------------------------------------
// PTX helpers (plain sm_80-level: valid on sm_103 without 'a' features)
// ---------------------------------------------------------------------------
__device__ __forceinline__ void cp_async16(uint32_t dst, const void* src) {
    asm volatile("cp.async.cg.shared.global [%0], [%1], 16;" :: "r"(dst), "l"(src));
}
__device__ __forceinline__ void cp_commit() {
    asm volatile("cp.async.commit_group;" ::: "memory");
}

__device__ __forceinline__ void ldsm_x4(uint32_t* r, uint32_t addr) {
    asm volatile("ldmatrix.sync.aligned.m8n8.x4.shared.b16 {%0,%1,%2,%3}, [%4];"
                 : "=r"(r[0]), "=r"(r[1]), "=r"(r[2]), "=r"(r[3]) : "r"(addr));
}

__device__ __forceinline__ void mma16816(float* d, const uint32_t* a,
                                         uint32_t b0, uint32_t b1) {
    asm volatile(
        "mma.sync.aligned.m16n8k16.row.col.f32.bf16.bf16.f32 "
        "{%0,%1,%2,%3}, {%4,%5,%6,%7}, {%8,%9}, {%0,%1,%2,%3};"
        : "+f"(d[0]), "+f"(d[1]), "+f"(d[2]), "+f"(d[3])
        : "r"(a[0]), "r"(a[1]), "r"(a[2]), "r"(a[3]), "r"(b0), "r"(b1));
}

// ---------------------------------------------------------------------------
// prep_A: transpose x [B,D,T] -> A bf16 [m=(b,t)][k], physical [Ahi|Alo]
//   k = seg*2048 + tap*1024 + d; tap0 = x[t-1] (0 at t=0), tap1 = x[t]
// ---------------------------------------------------------------------------
__global__ __launch_bounds__(256)
void prep_A_kernel(const float* __restrict__ x) {
    __shared__ float tile[32][33];
    const int b  = blockIdx.z;
    const int t0 = blockIdx.x * 32;
    const int d0 = blockIdx.y * 32;
    const int tx = threadIdx.x;      // 0..31
    const int ty = threadIdx.y;      // 0..7

#pragma unroll
    for (int i = 0; i < 4; ++i) {
        const int dl = ty + i * 8;
        tile[dl][tx] = x[((size_t)b * DDIM + d0 + dl) * TSEQ + t0 + tx];
    }
    __syncthreads();

#pragma unroll
    for (int i = 0; i < 4; ++i) {
        const int tl = ty + i * 8;
        const float v = tile[tx][tl];
        const __nv_bfloat16 hi = __float2bfloat16(v);
        const __nv_bfloat16 lo = __float2bfloat16(v - __bfloat162float(hi));
        const int t = t0 + tl;
        const int d = d0 + tx;
        const size_t m1 = (size_t)b * TSEQ + t;      // row using x[t] as tap1
        g_A[m1 * KA + 1024 + d]        = hi;
        g_A[m1 * KA + 2048 + 1024 + d] = lo;
        if (t + 1 < TSEQ) {                          // x[t] is tap0 of row t+1
            const size_t m0r = m1 + 1;
            g_A[m0r * KA + d]        = hi;
            g_A[m0r * KA + 2048 + d] = lo;
        }
        if (t == 0) {                                // causal pad: tap0 @ t=0
            const __nv_bfloat16 z = __float2bfloat16(0.f);
            g_A[m1 * KA + d]        = z;
            g_A[m1 * KA + 2048 + d] = z;
        }
    }
}

// ---------------------------------------------------------------------------
// prep_B: w [3H, D, 2] -> B bf16 [n][k], physical [Bhi|Blo]
// ---------------------------------------------------------------------------
__global__ __launch_bounds__(512)
void prep_B_kernel(const float* __restrict__ w) {
    const int idx = blockIdx.x * 512 + threadIdx.x;   // over 3072*1024
    const int n = idx >> 10;
    const int d = idx & 1023;
    const float2 wv = *(const float2*)&w[(size_t)idx * 2];   // w[n][d][0..1]
#pragma unroll
    for (int tap = 0; tap < 2; ++tap) {
        const float v = tap ? wv.y : wv.x;
        const __nv_bfloat16 hi = __float2bfloat16(v);
        const __nv_bfloat16 lo = __float2bfloat16(v - __bfloat162float(hi));
        const size_t base = (size_t)n * KB + tap * 1024 + d;
        g_B[base]        = hi;
        g_B[base + 2048] = lo;
    }
}

// ---------------------------------------------------------------------------
// GEMM: g_gates = act( A_cat @ B_cat^T + bias ), logical K = 6144 over
// physical dedup'd A/B. CTA 256x128, 512 threads (16 warps, 64x32 warp
// tiles), BK=64, 4-stage cp.async pipeline, bf16 mma.sync.
// smem tiles: K-major 128B rows with SW128 xor swizzle (ldmatrix-friendly).
// ---------------------------------------------------------------------------
__device__ __forceinline__ void fill_stage(int kt, int s, int tid,
                                           uint32_t smem_base, int m0, int n0) {
    // logical k-tile -> physical k offset (dedup'd hi segment)
    const int akt = (kt < 32) ? kt : kt - 32;   // [Ahi|Ahi|Alo] -> [Ahi|Alo]
    const int bkt = (kt < 64) ? kt : kt - 64;   // [Bhi|Blo|Bhi] -> [Bhi|Blo]
    const char* Abase = (const char*)g_A;
    const char* Bbase = (const char*)g_B;
#pragma unroll
    for (int i = 0; i < 4; ++i) {                    // A: 2048 x 16B
        const int c   = tid + i * 512;
        const int row = c >> 3;
        const int cb  = (c & 7) << 4;
        const uint32_t off = (row << 7) + cb;
        const uint32_t sw  = off ^ ((off >> 3) & 0x70);
        cp_async16(smem_base + SM_A_OFF(s) + sw,
                   Abase + ((size_t)(m0 + row) * KA + akt * 64) * 2 + cb);
    }
#pragma unroll
    for (int i = 0; i < 2; ++i) {                    // B: 1024 x 16B
        const int c   = tid + i * 512;
        const int row = c >> 3;
        const int cb  = (c & 7) << 4;
        const uint32_t off = (row << 7) + cb;
        const uint32_t sw  = off ^ ((off >> 3) & 0x70);
        cp_async16(smem_base + SM_B_OFF(s) + sw,
                   Bbase + ((size_t)(n0 + row) * KB + bkt * 64) * 2 + cb);
    }
    cp_commit();
}

__global__ __launch_bounds__(512, 1)
void qrnn_gemm_tc(const float* __restrict__ bias) {
    extern __shared__ __align__(1024) char smem[];
    const uint32_t smem_base = (uint32_t)__cvta_generic_to_shared(smem);
    const int tid = threadIdx.x;
    const int wid = tid >> 5;
    const int l   = tid & 31;
    const int n0 = blockIdx.x * TILE_N;   // n fastest: A m-panel + B L2 reuse
    const int m0 = blockIdx.y * TILE_M;

    const int warp_m = wid & 3;           // 4 warps over M (64 rows each)
    const int warp_n = wid >> 2;          // 4 warps over N (32 cols each)

    // ldmatrix lane geometry:
    //   r=l&7 row-within-8, (l>>3)&1 -> +8 row, (l>>4)&1 -> +16B col
    const int r      = l & 7;
    const int rsel   = (l >> 3) & 1;
    const int csel   = (l >> 4) & 1;
    const uint32_t xorv = (uint32_t)r << 4;          // SW128 xor term
    uint32_t kcx[4];
#pragma unroll
    for (int ks = 0; ks < 4; ++ks)
        kcx[ks] = ((uint32_t)(ks * 32 + 16 * csel)) ^ xorv;

    const uint32_t aRow = (uint32_t)(warp_m * 64 + r + 8 * rsel) << 7;
    const uint32_t bRow = (uint32_t)(warp_n * 32 + r + 8 * rsel) << 7;

    float acc[4][4][4];
#pragma unroll
    for (int mt = 0; mt < 4; ++mt)
#pragma unroll
        for (int nt = 0; nt < 4; ++nt)
#pragma unroll
            for (int q = 0; q < 4; ++q) acc[mt][nt][q] = 0.f;

    fill_stage(0, 0, tid, smem_base, m0, n0);
    fill_stage(1, 1, tid, smem_base, m0, n0);
    fill_stage(2, 2, tid, smem_base, m0, n0);

    for (int kt = 0; kt < NKITER; ++kt) {
        const int s = kt & 3;
        if (kt < NKITER - 2) {
            asm volatile("cp.async.wait_group 2;" ::: "memory");
        } else if (kt == NKITER - 2) {
            asm volatile("cp.async.wait_group 1;" ::: "memory");
        } else {
            asm volatile("cp.async.wait_group 0;" ::: "memory");
        }
        __syncthreads();

        const uint32_t aBase = smem_base + SM_A_OFF(s) + aRow;
        const uint32_t bBase = smem_base + SM_B_OFF(s) + bRow;

#pragma unroll
        for (int ks = 0; ks < 4; ++ks) {
            uint32_t a[4][4], bf[2][4];
#pragma unroll
            for (int mt = 0; mt < 4; ++mt)
                ldsm_x4(a[mt], aBase + mt * 2048 + kcx[ks]);
#pragma unroll
            for (int ng = 0; ng < 2; ++ng)
                ldsm_x4(bf[ng], bBase + ng * 2048 + kcx[ks]);
#pragma unroll
            for (int mt = 0; mt < 4; ++mt) {
#pragma unroll
                for (int ng = 0; ng < 2; ++ng) {
                    mma16816(acc[mt][2 * ng],     a[mt], bf[ng][0], bf[ng][2]);
                    mma16816(acc[mt][2 * ng + 1], a[mt], bf[ng][1], bf[ng][3]);
                }
            }
        }

        if (kt + 3 < NKITER)
            fill_stage(kt + 3, (kt + 3) & 3, tid, smem_base, m0, n0);
    }

    // ---- epilogue: bias + activation -> g_gates ----
    const int region = n0 >> 10;                 // 0=z(tanh), 1/2=sigmoid
    const int mW = m0 + warp_m * 64;
    const int nW = n0 + warp_n * 32;
#pragma unroll
    for (int mt = 0; mt < 4; ++mt) {
#pragma unroll
        for (int nt = 0; nt < 4; ++nt) {
            const int col  = nW + nt * 8 + 2 * (l & 3);
            const float b0 = bias[col];
            const float b1 = bias[col + 1];
#pragma unroll
            for (int half = 0; half < 2; ++half) {
                const int row = mW + mt * 16 + (l >> 2) + 8 * half;
                float gx = acc[mt][nt][2 * half]     + b0;
                float gy = acc[mt][nt][2 * half + 1] + b1;
                float vx, vy;
                if (region == 0) {
                    vx = 2.f / (1.f + __expf(-2.f * gx)) - 1.f;
                    vy = 2.f / (1.f + __expf(-2.f * gy)) - 1.f;
                } else {
                    vx = 1.f / (1.f + __expf(-gx));
                    vy = 1.f / (1.f + __expf(-gy));
                }
                *(float2*)&g_gates[(size_t)row * NCH + col] = make_float2(vx, vy);
            }
        }
    }
}

// ---------------------------------------------------------------------------
// Chunked fo-pooling scan: c_t = f*(c_{t-1} - z) + z ;  h_t = o*c_t
// 16 chunks of 64 per (b,h) chain -> 262K threads.
// ---------------------------------------------------------------------------
__global__ __launch_bounds__(256)
void qrnn_scan_pass1() {
    const int idx   = blockIdx.x * 256 + threadIdx.x;   // 0..262143
    const int b     = idx >> 14;
    const int chunk = (idx >> 10) & 15;
    const int h     = idx & 1023;
    const float* __restrict__ g =
        g_gates + ((size_t)(b * TSEQ + chunk * 64)) * NCH + h;
    float c = 0.f, F = 1.f;
#pragma unroll 4
    for (int t = 0; t < 64; ++t) {
        const float z = g[(size_t)t * NCH];
        const float f = g[(size_t)t * NCH + HDIM];
        c = f * (c - z) + z;
        F *= f;
    }
    const size_t st = ((size_t)(b * 1024 + h) * 16 + chunk) * 2;
    g_state[st]     = F;
    g_state[st + 1] = c;
}

__global__ __launch_bounds__(256)
void qrnn_scan_combine() {
    const int chain = blockIdx.x * 256 + threadIdx.x;   // 0..16383
    const float* st = g_state + (size_t)chain * 32;
    float* ci = g_cin + (size_t)chain * 16;
    float c = 0.f;
#pragma unroll
    for (int ch = 0; ch < 16; ++ch) {
        ci[ch] = c;
        c = st[ch * 2] * c + st[ch * 2 + 1];
    }
}

__global__ __launch_bounds__(256)
void qrnn_scan_pass2(float* __restrict__ out) {
    const int idx   = blockIdx.x * 256 + threadIdx.x;
    const int b     = idx >> 14;
    const int chunk = (idx >> 10) & 15;
    const int h     = idx & 1023;
    const float* __restrict__ g =
        g_gates + ((size_t)(b * TSEQ + chunk * 64)) * NCH + h;
    float* __restrict__ cout = out + ((size_t)b * TSEQ + chunk * 64) * HDIM + h;
    float* __restrict__ hout = cout + (size_t)BBATCH * TSEQ * HDIM;

    float c = g_cin[(size_t)(b * 1024 + h) * 16 + chunk];
#pragma unroll 4
    for (int t = 0; t < 64; ++t) {
        const float z = g[(size_t)t * NCH];
        const float f = g[(size_t)t * NCH + HDIM];
        const float o = g[(size_t)t * NCH + 2 * HDIM];
        c = f * (c - z) + z;
        cout[(size_t)t * HDIM] = c;
        hout[(size_t)t * HDIM] = o * c;
    }
}

// ---------------------------------------------------------------------------
extern "C" void kernel_launch(void* const* d_in, const int* in_sizes, int n_in,
                              void* d_out, int out_size)
{
    const float* x    = (const float*)d_in[0];   // [B, D, T]
    const float* w    = (const float*)d_in[1];   // [3H, D, 2]
    const float* bias = (const float*)d_in[2];   // [3H]
    float* out = (float*)d_out;

    cudaFuncSetAttribute(qrnn_gemm_tc, cudaFuncAttributeMaxDynamicSharedMemorySize,
                         GEMM_SMEM);

    prep_A_kernel<<<dim3(TSEQ / 32, DDIM / 32, BBATCH), dim3(32, 8)>>>(x);
    prep_B_kernel<<<(NCH * DDIM) / 512, 512>>>(w);

    qrnn_gemm_tc<<<dim3(NCH / TILE_N, MTOT / TILE_M), 512, GEMM_SMEM>>>(bias);

    qrnn_scan_pass1<<<(MTOT * 16) / 256, 256>>>();
    qrnn_scan_combine<<<MTOT / 256, 256>>>();
    qrnn_scan_pass2<<<(MTOT * 16) / 256, 256>>>(out);
}